// round 2
// baseline (speedup 1.0000x reference)
#include <cuda_runtime.h>
#include <cstdint>

// ---------------- problem constants ----------------
#define BATCH   128
#define G_TOT   10000
#define KW      20
#define LAT     2000
#define KDIM    30000      // G*C
#define INLEN   200000
#define NPAD    2048       // padded N for FC1 partials
#define KSPLIT  25
#define KLEN    1200       // 30000 / 25, multiple of 16

// ---------------- device scratch (static, no allocation) ----------------
__device__ float g_hT[(size_t)KDIM * 128];              // h transposed: [k=3g+c][b]
__device__ float g_zpart[(size_t)KSPLIT * NPAD * 128];  // FC1 split-K partials [s][n][m]
__device__ float g_zT[(size_t)LAT * 128];               // z transposed: [l][b]
__device__ float g_dT[(size_t)KDIM * 128];              // d transposed: [n=3g+c][b]

typedef unsigned long long u64;

// ---------------- packed f32x2 helpers (Blackwell FFMA2) ----------------
__device__ __forceinline__ u64 pack2(float x, float y) {
    u64 r; asm("mov.b64 %0, {%1, %2};" : "=l"(r) : "f"(x), "f"(y)); return r;
}
__device__ __forceinline__ void unpack2(u64 v, float& x, float& y) {
    asm("mov.b64 {%0, %1}, %2;" : "=f"(x), "=f"(y) : "l"(v));
}
__device__ __forceinline__ void fma2(u64& d, u64 a, u64 b) {
    asm("fma.rn.f32x2 %0, %1, %2, %0;" : "+l"(d) : "l"(a), "l"(b));
}

__device__ __forceinline__ float leaky(float v) { return v >= 0.0f ? v : 0.1f * v; }

// =====================================================================
// 1) Encoder grouped conv: h[b,g,c] = leaky(x[b,g,:20] . enc_w[g,c,:] + enc_b[g,c])
//    Output written TRANSPOSED: g_hT[(3g+c)*128 + b]  (k-major for the GEMM).
//    One CTA owns 64 groups, keeps weights in smem, loops over all 128 b,
//    stages a [192 k][32 b] tile in smem so global writes are coalesced.
// =====================================================================
#define GB 64
__global__ void enc_conv(const float* __restrict__ x,
                         const float* __restrict__ ew,
                         const float* __restrict__ eb) {
    __shared__ float w_s[GB * 60];
    __shared__ float b_s[GB * 3];
    __shared__ float x_s[GB * 20];
    __shared__ float ht_s[GB * 3 * 33];   // [k][bb] padded stride 33 (conflict-free)

    int g0 = blockIdx.x * GB;
    int ng = G_TOT - g0; if (ng > GB) ng = GB;
    int nk = ng * 3;
    int t  = threadIdx.x;

    for (int i = t; i < ng * 60; i += 256) w_s[i] = ew[(size_t)g0 * 60 + i];
    for (int i = t; i < nk;      i += 256) b_s[i] = eb[(size_t)g0 * 3 + i];
    __syncthreads();

    for (int bc = 0; bc < BATCH; bc += 32) {
        for (int bb = 0; bb < 32; bb++) {
            int b = bc + bb;
            for (int i = t; i < ng * 20; i += 256)
                x_s[i] = x[(size_t)b * INLEN + (size_t)g0 * 20 + i];
            __syncthreads();
            if (t < nk) {
                const float* wp = &w_s[t * 20];
                const float* xp = &x_s[(t / 3) * 20];
                float acc = b_s[t];
                #pragma unroll
                for (int k = 0; k < KW; k++) acc = fmaf(xp[k], wp[k], acc);
                ht_s[t * 33 + bb] = leaky(acc);
            }
            __syncthreads();
        }
        for (int e = t; e < nk * 32; e += 256) {
            int k = e >> 5, bb = e & 31;
            g_hT[(size_t)(g0 * 3 + k) * 128 + bc + bb] = ht_s[k * 33 + bb];
        }
        __syncthreads();
    }
}

// =====================================================================
// 2) GEMM: C[128, N] = AT[K,128]^T x W[N,K]^T   (128x128 tile per CTA, KC=16)
//    MODE 1: write fp32 partials to g_zpart[blockIdx.y][n][m]   (FC1, split-K)
//    MODE 2: fused bias + leaky, write transposed out[n*128+m]  (FC2)
//    Inner loop uses fma.rn.f32x2: acc pairs packed along m (adjacent in smem).
// =====================================================================
template <int MODE>
__global__ void __launch_bounds__(256, 2)
gemm128(const float* __restrict__ AT, const float* __restrict__ W,
        const float* __restrict__ bias, float* __restrict__ out,
        int N, int Kstride, int klen) {
    __shared__ __align__(16) float A_s[16 * 128];
    __shared__ __align__(16) float W_s[128 * 17];

    int t    = threadIdx.x;
    int n0   = blockIdx.x * 128;
    int kbeg = blockIdx.y * klen;
    int m_t  = t & 15;
    int n_t  = t >> 4;
    int mbase = m_t * 8;
    int nbase = n_t * 8;

    u64 acc[4][8];
    #pragma unroll
    for (int i = 0; i < 4; i++)
        #pragma unroll
        for (int j = 0; j < 8; j++) acc[i][j] = 0ull;   // (0.0f, 0.0f)

    int wj = t >> 1;            // W row within tile (0..127)
    int wq = t & 1;             // which 8-float half of the 16-k chunk
    const float* wrow = W + (size_t)(n0 + wj) * Kstride;
    bool wvalid = (n0 + wj) < N;

    for (int kc = 0; kc < klen; kc += 16) {
        int kk0 = kbeg + kc;
        // A tile [16][128] is fully contiguous in global (k-major layout)
        {
            const float4* asrc = (const float4*)(AT + (size_t)kk0 * 128);
            float4* adst = (float4*)A_s;
            adst[t]       = asrc[t];
            adst[t + 256] = asrc[t + 256];
        }
        // W tile: 128 rows x 16 k, 64B contiguous per row
        {
            float4 v0 = make_float4(0.f, 0.f, 0.f, 0.f), v1 = v0;
            if (wvalid) {
                v0 = *(const float4*)(wrow + kk0 + wq * 8);
                v1 = *(const float4*)(wrow + kk0 + wq * 8 + 4);
            }
            float* wd = &W_s[wj * 17 + wq * 8];
            wd[0] = v0.x; wd[1] = v0.y; wd[2] = v0.z; wd[3] = v0.w;
            wd[4] = v1.x; wd[5] = v1.y; wd[6] = v1.z; wd[7] = v1.w;
        }
        __syncthreads();
        #pragma unroll
        for (int kk = 0; kk < 16; kk++) {
            const u64* ap = (const u64*)&A_s[kk * 128 + mbase];
            u64 a0 = ap[0], a1 = ap[1], a2 = ap[2], a3 = ap[3];
            #pragma unroll
            for (int j = 0; j < 8; j++) {
                float w = W_s[(nbase + j) * 17 + kk];
                u64 w2 = pack2(w, w);
                fma2(acc[0][j], a0, w2);
                fma2(acc[1][j], a1, w2);
                fma2(acc[2][j], a2, w2);
                fma2(acc[3][j], a3, w2);
            }
        }
        __syncthreads();
    }

    if (MODE == 1) {
        // raw partials; n >= N columns are zero (W loaded as zero) and ignored later
        #pragma unroll
        for (int j = 0; j < 8; j++) {
            int n = n0 + nbase + j;
            u64* op = (u64*)(out + ((size_t)blockIdx.y * NPAD + n) * 128 + mbase);
            #pragma unroll
            for (int i = 0; i < 4; i++) op[i] = acc[i][j];
        }
    } else {
        #pragma unroll
        for (int j = 0; j < 8; j++) {
            int n = n0 + nbase + j;
            if (n < N) {
                float bv = bias[n];
                float* op = out + (size_t)n * 128 + mbase;
                #pragma unroll
                for (int i = 0; i < 4; i++) {
                    float xlo, xhi; unpack2(acc[i][j], xlo, xhi);
                    op[2 * i]     = leaky(xlo + bv);
                    op[2 * i + 1] = leaky(xhi + bv);
                }
            }
        }
    }
}

// =====================================================================
// 3) FC1 reduction: z_T[l][b] = leaky(sum_s partial[s][l][b] + enc_fc_b[l])
// =====================================================================
__global__ void reduce_z(const float* __restrict__ b1) {
    int n = blockIdx.x;
    int m = threadIdx.x;
    float s = b1[n];
    #pragma unroll
    for (int ks = 0; ks < KSPLIT; ks++)
        s += g_zpart[((size_t)ks * NPAD + n) * 128 + m];
    g_zT[(size_t)n * 128 + m] = leaky(s);
}

// =====================================================================
// 4) Decoder grouped deconv + sigmoid:
//    out[b, g*20+k] = sigmoid(sum_c dT[3g+c][b] * dec_w[g,c,k] + dec_b[g])
//    CTA owns 64 groups, weights resident; stages a [192][32 b] tile of dT.
// =====================================================================
__global__ void dec_conv(const float* __restrict__ dw,
                         const float* __restrict__ db,
                         float* __restrict__ out) {
    __shared__ float w_s[GB * 60];
    __shared__ float b_s[GB];
    __shared__ float dt_s[GB * 3 * 33];

    int g0 = blockIdx.x * GB;
    int ng = G_TOT - g0; if (ng > GB) ng = GB;
    int nk = ng * 3;
    int t  = threadIdx.x;

    for (int i = t; i < ng * 60; i += 256) w_s[i] = dw[(size_t)g0 * 60 + i];
    for (int i = t; i < ng;      i += 256) b_s[i] = db[g0 + i];
    __syncthreads();

    for (int bc = 0; bc < BATCH; bc += 32) {
        for (int e = t; e < nk * 32; e += 256) {
            int k = e >> 5, bb = e & 31;
            dt_s[k * 33 + bb] = g_dT[(size_t)(g0 * 3 + k) * 128 + bc + bb];
        }
        __syncthreads();
        for (int bb = 0; bb < 32; bb++) {
            int b = bc + bb;
            for (int idx = t; idx < ng * 20; idx += 256) {
                int g  = idx / 20;
                int kk = idx - g * 20;
                float v = fmaf(dt_s[(g * 3 + 0) * 33 + bb], w_s[g * 60 +      kk],
                          fmaf(dt_s[(g * 3 + 1) * 33 + bb], w_s[g * 60 + 20 + kk],
                          fmaf(dt_s[(g * 3 + 2) * 33 + bb], w_s[g * 60 + 40 + kk],
                               b_s[g])));
                out[(size_t)b * INLEN + (size_t)g0 * 20 + idx] =
                    1.0f / (1.0f + __expf(-v));
            }
        }
        __syncthreads();
    }
}

// =====================================================================
// launcher — graph-capturable, allocation-free
// =====================================================================
extern "C" void kernel_launch(void* const* d_in, const int* in_sizes, int n_in,
                              void* d_out, int out_size) {
    const float* x   = (const float*)d_in[0];
    const float* ew  = (const float*)d_in[1];
    const float* eb  = (const float*)d_in[2];
    const float* efw = (const float*)d_in[3];
    const float* efb = (const float*)d_in[4];
    const float* dfw = (const float*)d_in[5];
    const float* dfb = (const float*)d_in[6];
    const float* dw  = (const float*)d_in[7];
    const float* db  = (const float*)d_in[8];
    float* out = (float*)d_out;

    float *hT, *zpart, *zT, *dT;
    cudaGetSymbolAddress((void**)&hT,    g_hT);
    cudaGetSymbolAddress((void**)&zpart, g_zpart);
    cudaGetSymbolAddress((void**)&zT,    g_zT);
    cudaGetSymbolAddress((void**)&dT,    g_dT);

    // 1) encoder grouped conv -> h^T
    enc_conv<<<(G_TOT + GB - 1) / GB, 256>>>(x, ew, eb);
    // 2) FC1 (split-K=25) -> partials
    gemm128<1><<<dim3(16, KSPLIT), 256>>>(hT, efw, nullptr, zpart, LAT, KDIM, KLEN);
    // 3) reduce + bias + leaky -> z^T
    reduce_z<<<LAT, 128>>>(efb);
    // 4) FC2 fused bias+leaky -> d^T
    gemm128<2><<<dim3((KDIM + 127) / 128, 1), 256>>>(zT, dfw, dfb, dT, KDIM, LAT, LAT);
    // 5) decoder deconv + sigmoid -> out
    dec_conv<<<(G_TOT + GB - 1) / GB, 256>>>(dw, db, out);
}

// round 8
// speedup vs baseline: 1.6860x; 1.6860x over previous
#include <cuda_runtime.h>
#include <cuda_bf16.h>
#include <cstdint>

// ---------------- problem constants ----------------
#define BATCH   128
#define G_TOT   10000
#define KW      20
#define LAT     2000
#define KDIM    30000      // G*C
#define INLEN   200000
#define NPAD    2048
#define SPLIT_LEN 1216     // FC1 split-K length (19 blocks of 64)
#define KSPLIT  25         // last split = 816
#define NBLK_H  469        // ceil(30000/64)
#define NBLK_Z  32         // ceil(2000/64)

// Per 64-k block: [128 m][64 k] bf16, SW128 swizzled rows; hi 16KB then lo 16KB.
#define ABLK_BYTES 32768

// ---------------- device scratch (static, no allocation) ----------------
__device__ __align__(16) unsigned char g_hA[(size_t)NBLK_H * ABLK_BYTES];
__device__ __align__(16) unsigned char g_zA[(size_t)NBLK_Z * ABLK_BYTES];
__device__ float g_zpart[(size_t)KSPLIT * NPAD * 128];
__device__ float g_dT[(size_t)KDIM * 128];

// ---------------- helpers ----------------
__device__ __forceinline__ uint32_t smem_u32(const void* p) {
    uint32_t a;
    asm("{ .reg .u64 t; cvta.to.shared.u64 t, %1; cvt.u32.u64 %0, t; }" : "=r"(a) : "l"(p));
    return a;
}
__device__ __forceinline__ uint32_t swz128(uint32_t off) { return off ^ ((off >> 3) & 0x70); }
__device__ __forceinline__ float leaky(float v) { return v >= 0.0f ? v : 0.1f * v; }

// pack two fp32 -> bf16x2 (lo half = a, hi half = b)
__device__ __forceinline__ uint32_t bf2pack(float a, float b) {
    uint32_t r;
    asm("cvt.rn.bf16x2.f32 %0, %1, %2;" : "=r"(r) : "f"(b), "f"(a));
    return r;
}

__device__ __forceinline__ void ldsm4(uint32_t* r, uint32_t addr) {
    asm volatile("ldmatrix.sync.aligned.m8n8.x4.shared.b16 {%0,%1,%2,%3}, [%4];"
        : "=r"(r[0]), "=r"(r[1]), "=r"(r[2]), "=r"(r[3]) : "r"(addr));
}

__device__ __forceinline__ void mma16816(float* c, const uint32_t* a, uint32_t b0, uint32_t b1) {
    asm volatile("mma.sync.aligned.m16n8k16.row.col.f32.bf16.bf16.f32 "
        "{%0,%1,%2,%3}, {%4,%5,%6,%7}, {%8,%9}, {%0,%1,%2,%3};"
        : "+f"(c[0]), "+f"(c[1]), "+f"(c[2]), "+f"(c[3])
        : "r"(a[0]), "r"(a[1]), "r"(a[2]), "r"(a[3]), "r"(b0), "r"(b1));
}

__device__ __forceinline__ void cpasync16(uint32_t dst, const void* src) {
    asm volatile("cp.async.cg.shared.global [%0], [%1], 16;" :: "r"(dst), "l"(src));
}
#define CP_COMMIT() asm volatile("cp.async.commit_group;" ::: "memory")
#define CP_WAIT0()  asm volatile("cp.async.wait_group 0;" ::: "memory")

// =====================================================================
// 1) Encoder grouped conv -> A-format (bf16 hi/lo, SW128-swizzled) in g_hA
// =====================================================================
#define GB 64
__global__ void enc_conv(const float* __restrict__ x,
                         const float* __restrict__ ew,
                         const float* __restrict__ eb) {
    __shared__ float w_s[GB * 60];
    __shared__ float b_s[GB * 3];
    __shared__ float x_s[GB * 20];
    __shared__ float ht_s[GB * 3 * 33];

    int g0 = blockIdx.x * GB;
    int ng = G_TOT - g0; if (ng > GB) ng = GB;
    int nk = ng * 3;
    int k0 = g0 * 3;                 // multiple of 192
    int t  = threadIdx.x;

    for (int i = t; i < ng * 60; i += 256) w_s[i] = ew[(size_t)g0 * 60 + i];
    for (int i = t; i < nk;      i += 256) b_s[i] = eb[(size_t)g0 * 3 + i];
    __syncthreads();

    for (int bc = 0; bc < BATCH; bc += 32) {
        for (int bb = 0; bb < 32; bb++) {
            int b = bc + bb;
            for (int i = t; i < ng * 20; i += 256)
                x_s[i] = x[(size_t)b * INLEN + (size_t)g0 * 20 + i];
            __syncthreads();
            if (t < nk) {
                const float* wp = &w_s[t * 20];
                const float* xp = &x_s[(t / 3) * 20];
                float acc = b_s[t];
                #pragma unroll
                for (int k = 0; k < KW; k++) acc = fmaf(xp[k], wp[k], acc);
                ht_s[t * 33 + bb] = leaky(acc);
            }
            __syncthreads();
        }
        int npair = nk >> 1;
        for (int idx = t; idx < npair * 32; idx += 256) {
            int kp = idx % npair;
            int bb = idx / npair;
            int m  = bc + bb;
            float v0 = ht_s[(2 * kp)     * 33 + bb];
            float v1 = ht_s[(2 * kp + 1) * 33 + bb];
            uint32_t hi = bf2pack(v0, v1);
            float h0 = __uint_as_float(hi << 16);
            float h1 = __uint_as_float(hi & 0xffff0000u);
            uint32_t lo = bf2pack(v0 - h0, v1 - h1);
            int k   = 2 * kp;
            int blk = (k0 + k) >> 6;
            int kin = k & 63;
            uint32_t off = swz128((uint32_t)m * 128 + (uint32_t)(kin << 1));
            unsigned char* base = g_hA + (size_t)blk * ABLK_BYTES;
            *(uint32_t*)(base + off)         = hi;
            *(uint32_t*)(base + 16384 + off) = lo;
        }
        __syncthreads();
    }
}

// =====================================================================
// 2) Tensor-core GEMM via mma.sync (bf16 hi/lo, 3-pass, fp32 accum)
//    D[128 m, 128 n-tile] = A[128,K] * W[N,K]^T
//    MODE 1: fp32 partials -> g_zpart[by][n][m]   (FC1 split-K)
//    MODE 2: fused bias + leaky -> out[n*128+m]   (FC2)
// =====================================================================
#define SMEM_GEMM (2 * 65536)

template <int MODE>
__global__ void __launch_bounds__(256, 1)
gemm_mma(const unsigned char* __restrict__ Aglob,
         const float* __restrict__ W,
         const float* __restrict__ bias,
         float* __restrict__ out,
         int N, int Kstride, int totalK, int splitLen) {
    extern __shared__ __align__(1024) unsigned char sm[];
    uint32_t smb = smem_u32(sm);
    int t = threadIdx.x, wid = t >> 5, L = t & 31;

    int n0   = blockIdx.x * 128;
    int kbeg = blockIdx.y * splitLen;
    int klen = min(splitLen, totalK - kbeg);
    int S    = (klen + 63) >> 6;
    int blk0 = kbeg >> 6;

    // W load assignment: 2 threads per n-row, each covers 32 k as 8 float4
    int wn = t >> 1;
    int wh = t & 1;
    const float* wrow = W + (size_t)(n0 + wn) * Kstride + kbeg;
    bool rvalid = (n0 + wn) < N;
    uint32_t wsoff[8];
    #pragma unroll
    for (int f = 0; f < 8; f++)
        wsoff[f] = swz128((uint32_t)wn * 128 + (uint32_t)((wh * 32 + f * 4) << 1));

    // ldmatrix per-lane addressing.
    // Correct SW128 form: addr = row*128 + ((kbyte) ^ ((row&7)<<4)).
    // kbyte = kb0 + ks*32 <= 112 (no carry), so the XOR must be applied to the
    // FULL k byte offset per step — never add k offsets after swizzling.
    int m0w = (wid >> 2) * 64;
    int nw0 = (wid & 3) * 32;
    uint32_t aRowOff = (uint32_t)(m0w + (L & 15)) * 128;
    uint32_t bRowOff = (uint32_t)(nw0 + (L & 15)) * 128;
    uint32_t pat     = (uint32_t)(L & 7) << 4;          // row&7 pattern (same for A and B)
    uint32_t kb0     = (uint32_t)(L >> 4) << 4;         // 0 or 16 bytes

    float acc[4][4][4];
    #pragma unroll
    for (int i = 0; i < 4; i++)
        #pragma unroll
        for (int j = 0; j < 4; j++)
            #pragma unroll
            for (int q = 0; q < 4; q++) acc[i][j][q] = 0.0f;

    // ---- prolog: stage 0 A via cp.async, W0 into regs ----
    float4 aW[8];
    {
        const char* src = (const char*)(Aglob + (size_t)blk0 * ABLK_BYTES) + t * 16;
        uint32_t dst = smb + t * 16;
        #pragma unroll
        for (int i = 0; i < 8; i++) cpasync16(dst + i * 4096, src + i * 4096);
        CP_COMMIT();
        #pragma unroll
        for (int f = 0; f < 8; f++) {
            int kk = wh * 32 + f * 4;
            aW[f] = (rvalid && kk < klen) ? *(const float4*)(wrow + kk)
                                          : make_float4(0.f, 0.f, 0.f, 0.f);
        }
    }

    for (int s = 0; s < S; s++) {
        uint32_t bufo = (uint32_t)(s & 1) * 65536;
        int lenS = min(64, klen - (s << 6));

        CP_WAIT0();   // stage-s A tile arrived

        // store W_s (convert fp32 -> bf16 hi/lo, swizzled)
        #pragma unroll
        for (int f = 0; f < 8; f++) {
            float x0 = aW[f].x, x1 = aW[f].y, x2 = aW[f].z, x3 = aW[f].w;
            uint32_t h01 = bf2pack(x0, x1);
            uint32_t h23 = bf2pack(x2, x3);
            float f0 = __uint_as_float(h01 << 16);
            float f1 = __uint_as_float(h01 & 0xffff0000u);
            float f2 = __uint_as_float(h23 << 16);
            float f3 = __uint_as_float(h23 & 0xffff0000u);
            uint32_t l01 = bf2pack(x0 - f0, x1 - f1);
            uint32_t l23 = bf2pack(x2 - f2, x3 - f3);
            *(uint2*)(sm + bufo + 32768 + wsoff[f]) = make_uint2(h01, h23);
            *(uint2*)(sm + bufo + 49152 + wsoff[f]) = make_uint2(l01, l23);
        }
        __syncthreads();

        // prefetch stage s+1
        if (s + 1 < S) {
            uint32_t nbufo = (uint32_t)((s + 1) & 1) * 65536;
            const char* src = (const char*)(Aglob + (size_t)(blk0 + s + 1) * ABLK_BYTES) + t * 16;
            uint32_t dst = smb + nbufo + t * 16;
            #pragma unroll
            for (int i = 0; i < 8; i++) cpasync16(dst + i * 4096, src + i * 4096);
            CP_COMMIT();
            int koff = (s + 1) << 6;
            #pragma unroll
            for (int f = 0; f < 8; f++) {
                int kk = koff + wh * 32 + f * 4;
                aW[f] = (rvalid && kk < klen) ? *(const float4*)(wrow + kk)
                                              : make_float4(0.f, 0.f, 0.f, 0.f);
            }
        }

        // ---- compute stage s ----
        uint32_t aBase = smb + bufo + aRowOff;            // A hi tile
        uint32_t bBase = smb + bufo + 32768 + bRowOff;    // W hi tile
        int nk16 = lenS >> 4;
        for (int ks = 0; ks < nk16; ks++) {
            uint32_t kx = (kb0 + (uint32_t)ks * 32) ^ pat;   // swizzled within-row k offset
            uint32_t Ah[4][4], Al[4][4], Bh[2][4], Bl[2][4];
            #pragma unroll
            for (int i = 0; i < 4; i++) {
                ldsm4(Ah[i], aBase + i * 2048 + kx);
                ldsm4(Al[i], aBase + 16384 + i * 2048 + kx);
            }
            #pragma unroll
            for (int p = 0; p < 2; p++) {
                ldsm4(Bh[p], bBase + p * 2048 + kx);
                ldsm4(Bl[p], bBase + 16384 + p * 2048 + kx);
            }
            #pragma unroll
            for (int i = 0; i < 4; i++)
                #pragma unroll
                for (int j = 0; j < 4; j++) {
                    int p = j >> 1, q = j & 1;
                    mma16816(acc[i][j], Ah[i], Bh[p][q], Bh[p][q + 2]);
                    mma16816(acc[i][j], Ah[i], Bl[p][q], Bl[p][q + 2]);
                    mma16816(acc[i][j], Al[i], Bh[p][q], Bh[p][q + 2]);
                }
        }
        __syncthreads();
    }

    // ---- epilogue: write accumulators ----
    int row0 = m0w + (L >> 2);
    int col0 = nw0 + (L & 3) * 2;
    #pragma unroll
    for (int i = 0; i < 4; i++)
        #pragma unroll
        for (int j = 0; j < 4; j++) {
            int row = row0 + i * 16;
            int col = col0 + j * 8;
            if (MODE == 1) {
                float* base = out + ((size_t)blockIdx.y * NPAD + (n0 + col)) * 128 + row;
                base[0]   = acc[i][j][0];
                base[128] = acc[i][j][1];
                base[8]   = acc[i][j][2];
                base[136] = acc[i][j][3];
            } else {
                int n = n0 + col;
                if (n < N) {
                    float b0 = bias[n];
                    out[(size_t)n * 128 + row]     = leaky(acc[i][j][0] + b0);
                    out[(size_t)n * 128 + row + 8] = leaky(acc[i][j][2] + b0);
                }
                if (n + 1 < N) {
                    float b1 = bias[n + 1];
                    out[(size_t)(n + 1) * 128 + row]     = leaky(acc[i][j][1] + b1);
                    out[(size_t)(n + 1) * 128 + row + 8] = leaky(acc[i][j][3] + b1);
                }
            }
        }
}

// =====================================================================
// 3) FC1 reduction + bias + leaky -> z in A-format (bf16 hi/lo) g_zA
// =====================================================================
__global__ void reduce_z(const float* __restrict__ b1) {
    int n = blockIdx.x;
    int m = threadIdx.x;
    float s = b1[n];
    #pragma unroll
    for (int ks = 0; ks < KSPLIT; ks++)
        s += g_zpart[((size_t)ks * NPAD + n) * 128 + m];
    float val = leaky(s);
    __nv_bfloat16 hi = __float2bfloat16(val);
    __nv_bfloat16 lo = __float2bfloat16(val - __bfloat162float(hi));
    int blk = n >> 6;
    int kin = n & 63;
    uint32_t off = swz128((uint32_t)m * 128 + (uint32_t)(kin << 1));
    unsigned char* base = g_zA + (size_t)blk * ABLK_BYTES;
    *(__nv_bfloat16*)(base + off)         = hi;
    *(__nv_bfloat16*)(base + 16384 + off) = lo;
}

// =====================================================================
// 4) Decoder grouped deconv + sigmoid
// =====================================================================
__global__ void dec_conv(const float* __restrict__ dw,
                         const float* __restrict__ db,
                         float* __restrict__ out) {
    __shared__ float w_s[GB * 60];
    __shared__ float b_s[GB];
    __shared__ float dt_s[GB * 3 * 33];

    int g0 = blockIdx.x * GB;
    int ng = G_TOT - g0; if (ng > GB) ng = GB;
    int nk = ng * 3;
    int t  = threadIdx.x;

    for (int i = t; i < ng * 60; i += 256) w_s[i] = dw[(size_t)g0 * 60 + i];
    for (int i = t; i < ng;      i += 256) b_s[i] = db[g0 + i];
    __syncthreads();

    for (int bc = 0; bc < BATCH; bc += 32) {
        for (int e = t; e < nk * 32; e += 256) {
            int k = e >> 5, bb = e & 31;
            dt_s[k * 33 + bb] = g_dT[(size_t)(g0 * 3 + k) * 128 + bc + bb];
        }
        __syncthreads();
        for (int bb = 0; bb < 32; bb++) {
            int b = bc + bb;
            for (int idx = t; idx < ng * 20; idx += 256) {
                int g  = idx / 20;
                int kk = idx - g * 20;
                float v = fmaf(dt_s[(g * 3 + 0) * 33 + bb], w_s[g * 60 +      kk],
                          fmaf(dt_s[(g * 3 + 1) * 33 + bb], w_s[g * 60 + 20 + kk],
                          fmaf(dt_s[(g * 3 + 2) * 33 + bb], w_s[g * 60 + 40 + kk],
                               b_s[g])));
                out[(size_t)b * INLEN + (size_t)g0 * 20 + idx] =
                    1.0f / (1.0f + __expf(-v));
            }
        }
        __syncthreads();
    }
}

// =====================================================================
// launcher — graph-capturable, allocation-free
// =====================================================================
extern "C" void kernel_launch(void* const* d_in, const int* in_sizes, int n_in,
                              void* d_out, int out_size) {
    const float* x   = (const float*)d_in[0];
    const float* ew  = (const float*)d_in[1];
    const float* eb  = (const float*)d_in[2];
    const float* efw = (const float*)d_in[3];
    const float* efb = (const float*)d_in[4];
    const float* dfw = (const float*)d_in[5];
    const float* dfb = (const float*)d_in[6];
    const float* dw  = (const float*)d_in[7];
    const float* db  = (const float*)d_in[8];
    float* out = (float*)d_out;

    unsigned char *hA, *zA;
    float *zpart, *dT;
    cudaGetSymbolAddress((void**)&hA,    g_hA);
    cudaGetSymbolAddress((void**)&zA,    g_zA);
    cudaGetSymbolAddress((void**)&zpart, g_zpart);
    cudaGetSymbolAddress((void**)&dT,    g_dT);

    cudaFuncSetAttribute(gemm_mma<1>, cudaFuncAttributeMaxDynamicSharedMemorySize, SMEM_GEMM);
    cudaFuncSetAttribute(gemm_mma<2>, cudaFuncAttributeMaxDynamicSharedMemorySize, SMEM_GEMM);

    // 1) encoder grouped conv -> h (bf16 hi/lo, A-format)
    enc_conv<<<(G_TOT + GB - 1) / GB, 256>>>(x, ew, eb);
    // 2) FC1 mma GEMM (split-K) -> fp32 partials
    gemm_mma<1><<<dim3(16, KSPLIT), 256, SMEM_GEMM>>>(hA, efw, nullptr, zpart,
                                                      LAT, KDIM, KDIM, SPLIT_LEN);
    // 3) reduce + bias + leaky -> z (bf16 hi/lo, A-format)
    reduce_z<<<LAT, 128>>>(efb);
    // 4) FC2 mma GEMM, fused bias+leaky -> d^T (fp32)
    gemm_mma<2><<<dim3((KDIM + 127) / 128, 1), 256, SMEM_GEMM>>>(zA, dfw, dfb, dT,
                                                                 KDIM, LAT, LAT, 2048);
    // 5) decoder deconv + sigmoid -> out
    dec_conv<<<(G_TOT + GB - 1) / GB, 256>>>(dw, db, out);
}